// round 8
// baseline (speedup 1.0000x reference)
#include <cuda_runtime.h>
#include <cuda_bf16.h>

// BilinearInterpolation (spatial transformer grid sample)
// X: [B, C, H, W] fp32, theta: [B, 6] fp32 -> out: [B, C, H_OUT, W_OUT] fp32
//
// R7: shared-memory staging. Block = 32x32 output tile x 16 channels.
// The affine map is linear, so the tile's sample-coordinate extremes are at
// the tile corners; bbox = clamp(corner extremes) + 1px fp-safety pad.
// Per channel: coalesced-copy the bbox into smem, then bilinear-gather via
// LDS. Staged values are bit-exact copies and the per-pixel weight chain is
// identical to R2-R4, so output must stay bit-identical (rel_err 9.128e-4).
// Clamped border tiles get tiny bboxes automatically. Blocks whose bbox
// exceeds the smem cap (extreme theta, block-uniform condition) fall back
// to direct global gathers.

namespace {
constexpr int B = 16, C = 64, H = 256, W = 256;
constexpr int H_OUT = 256, W_OUT = 256;
constexpr int HW  = H * W;
constexpr int HWO = H_OUT * W_OUT;
constexpr int TILE = 32;            // 32x32 output tile
constexpr int CG   = 16;            // channels per block
constexpr int NCG  = C / CG;        // 4
constexpr int NTX  = W_OUT / TILE;  // 8
constexpr int NTY  = H_OUT / TILE;  // 8
constexpr int SMEM_FLOATS = 12160;  // 48640 B <= 48KB static limit
}

__global__ __launch_bounds__(256, 4)
void bilerp_kernel(const float* __restrict__ X,
                   const float* __restrict__ theta,
                   float* __restrict__ out) {
    __shared__ float tile_s[SMEM_FLOATS];

    // blockIdx = b*256 + tile*4 + cg
    const int cg = blockIdx.x & (NCG - 1);
    const int t  = (blockIdx.x >> 2) & 63;
    const int b  = blockIdx.x >> 8;
    const int tx = (t & (NTX - 1)) * TILE;
    const int ty = (t >> 3) * TILE;

    const int lane = threadIdx.x & 31;
    const int w    = threadIdx.x >> 5;   // 0..7

    const float* th = theta + b * 6;
    const float t00 = __ldg(th + 0), t01 = __ldg(th + 1), t02 = __ldg(th + 2);
    const float t10 = __ldg(th + 3), t11 = __ldg(th + 4), t12 = __ldg(th + 5);

    // ---- per-pixel precompute (channel-invariant), 4 px per thread ----
    // thread -> pixels (tx+lane, ty + w + 8*i), i = 0..3
    int   px0[4], px1[4], py0[4], py1[4];
    float wA[4], wB[4], wC[4], wD[4];
    #pragma unroll
    for (int i = 0; i < 4; ++i) {
        const int ix = tx + lane;
        const int iy = ty + w + 8 * i;

        const float xc = fmaf((float)ix, 2.0f / (float)(W_OUT - 1), -1.0f);
        const float yc = fmaf((float)iy, 2.0f / (float)(H_OUT - 1), -1.0f);
        const float xs = t00 * xc + t01 * yc + t02;
        const float ys = t10 * xc + t11 * yc + t12;
        const float x  = (xs + 1.0f) * ((float)W * 0.5f);
        const float y  = (ys + 1.0f) * ((float)H * 0.5f);

        int x0 = (int)floorf(x);
        int x1 = x0 + 1;
        int y0 = (int)floorf(y);
        int y1 = y0 + 1;
        x0 = min(max(x0, 0), W - 1);
        x1 = min(max(x1, 0), W - 1);
        y0 = min(max(y0, 0), H - 1);
        y1 = min(max(y1, 0), H - 1);

        const float x0f = (float)x0, x1f = (float)x1;
        const float y0f = (float)y0, y1f = (float)y1;
        wA[i] = (x1f - x) * (y1f - y);
        wB[i] = (x1f - x) * (y - y0f);
        wC[i] = (x - x0f) * (y1f - y);
        wD[i] = (x - x0f) * (y - y0f);
        px0[i] = x0; px1[i] = x1; py0[i] = y0; py1[i] = y1;
    }

    // ---- tile bbox from the 4 tile corners (map is linear) + 1px pad ----
    const float cxl = fmaf((float)tx,            2.0f / 255.0f, -1.0f);
    const float cxh = fmaf((float)(tx + 31),     2.0f / 255.0f, -1.0f);
    const float cyl = fmaf((float)ty,            2.0f / 255.0f, -1.0f);
    const float cyh = fmaf((float)(ty + 31),     2.0f / 255.0f, -1.0f);

    float xmn = 3.0e38f, xmx = -3.0e38f, ymn = 3.0e38f, ymx = -3.0e38f;
    #pragma unroll
    for (int k = 0; k < 4; ++k) {
        const float xck = (k & 1) ? cxh : cxl;
        const float yck = (k & 2) ? cyh : cyl;
        const float xs = t00 * xck + t01 * yck + t02;
        const float ys = t10 * xck + t11 * yck + t12;
        const float xx = (xs + 1.0f) * 128.0f;
        const float yy = (ys + 1.0f) * 128.0f;
        xmn = fminf(xmn, xx); xmx = fmaxf(xmx, xx);
        ymn = fminf(ymn, yy); ymx = fmaxf(ymx, yy);
    }
    const int xlo = min(max((int)floorf(xmn) - 1, 0), W - 1);
    const int xhi = min(max((int)floorf(xmx) + 2, 0), W - 1);
    const int ylo = min(max((int)floorf(ymn) - 1, 0), H - 1);
    const int yhi = min(max((int)floorf(ymx) + 2, 0), H - 1);
    const int bw  = xhi - xlo + 1;
    const int bh  = yhi - ylo + 1;
    const int bwp = bw | 1;              // odd pad vs LDS bank conflicts

    const float* __restrict__ xbase = X   + ((size_t)(b * C + cg * CG)) * HW;
    float*       __restrict__ obase = out + ((size_t)(b * C + cg * CG)) * HWO;

    const bool fits = (bwp * bh <= SMEM_FLOATS);   // block-uniform

    if (fits) {
        // local (smem) gather offsets, channel-invariant
        int la[4], lb[4], lc[4], ld[4];
        #pragma unroll
        for (int i = 0; i < 4; ++i) {
            la[i] = (py0[i] - ylo) * bwp + (px0[i] - xlo);
            lb[i] = (py1[i] - ylo) * bwp + (px0[i] - xlo);
            lc[i] = (py0[i] - ylo) * bwp + (px1[i] - xlo);
            ld[i] = (py1[i] - ylo) * bwp + (px1[i] - xlo);
        }
        const int obase_px = ty + w;     // row of i=0

        for (int c = 0; c < CG; ++c) {
            __syncthreads();             // prior channel's gathers done
            // stage bbox: warp w copies rows w, w+8, ... (coalesced)
            const float* src = xbase + (size_t)c * HW + (size_t)ylo * W + xlo;
            for (int r = w; r < bh; r += 8) {
                const float* sr = src + (size_t)r * W;
                float* dr = tile_s + r * bwp;
                for (int q = lane; q < bw; q += 32)
                    dr[q] = __ldg(sr + q);
            }
            __syncthreads();

            float* op = obase + (size_t)c * HWO + (size_t)obase_px * W_OUT + tx + lane;
            #pragma unroll
            for (int i = 0; i < 4; ++i) {
                const float pa = tile_s[la[i]];
                const float pb = tile_s[lb[i]];
                const float pc = tile_s[lc[i]];
                const float pd = tile_s[ld[i]];
                op[(size_t)(8 * i) * W_OUT] =
                    wA[i] * pa + wB[i] * pb + wC[i] * pc + wD[i] * pd;
            }
        }
    } else {
        // fallback: direct global gathers (rare: extreme theta)
        int ga[4], gb[4], gc[4], gd[4];
        #pragma unroll
        for (int i = 0; i < 4; ++i) {
            ga[i] = py0[i] * W + px0[i];
            gb[i] = py1[i] * W + px0[i];
            gc[i] = py0[i] * W + px1[i];
            gd[i] = py1[i] * W + px1[i];
        }
        for (int c = 0; c < CG; ++c) {
            const float* p = xbase + (size_t)c * HW;
            float* op = obase + (size_t)c * HWO + (size_t)(ty + w) * W_OUT + tx + lane;
            #pragma unroll
            for (int i = 0; i < 4; ++i) {
                const float pa = __ldg(p + ga[i]);
                const float pb = __ldg(p + gb[i]);
                const float pc = __ldg(p + gc[i]);
                const float pd = __ldg(p + gd[i]);
                op[(size_t)(8 * i) * W_OUT] =
                    wA[i] * pa + wB[i] * pb + wC[i] * pc + wD[i] * pd;
            }
        }
    }
}

extern "C" void kernel_launch(void* const* d_in, const int* in_sizes, int n_in,
                              void* d_out, int out_size) {
    const float* X     = (const float*)d_in[0];
    const float* theta = (const float*)d_in[1];
    if (n_in >= 2 && in_sizes[0] == B * 6) {
        theta = (const float*)d_in[0];
        X     = (const float*)d_in[1];
    }
    float* out = (float*)d_out;

    dim3 grid(B * NTY * NTX * NCG);   // 4096 blocks
    dim3 block(256);
    bilerp_kernel<<<grid, block>>>(X, theta, out);
}

// round 9
// speedup vs baseline: 1.0517x; 1.0517x over previous
#include <cuda_runtime.h>
#include <cuda_bf16.h>

// BilinearInterpolation (spatial transformer grid sample)
// X: [B, C, H, W] fp32, theta: [B, 6] fp32 -> out: [B, C, H_OUT, W_OUT] fp32
//
// R8 = R7 (smem staging) with the latency bugs fixed:
//  - double-buffered staging (2 x 6080 floats): stage channel c+1 while
//    gathering channel c  -> staging LDG latency overlapped
//  - ONE __syncthreads per channel (ping-pong buffers)
//  - fallback path (bbox too big) uses the R4-winning 8x4 warp patch
// Staged values are bit-exact copies; weight chain identical to R2-R4,
// so rel_err must stay exactly 9.128e-4.

namespace {
constexpr int B = 16, C = 64, H = 256, W = 256;
constexpr int H_OUT = 256, W_OUT = 256;
constexpr int HW  = H * W;
constexpr int HWO = H_OUT * W_OUT;
constexpr int TILE = 32;            // 32x32 output tile
constexpr int CG   = 16;            // channels per block
constexpr int NCG  = C / CG;        // 4
constexpr int NTX  = W_OUT / TILE;  // 8
constexpr int BUF  = 6080;          // floats per staging buffer (2 bufs = 47.5KB)
}

__global__ __launch_bounds__(256, 4)
void bilerp_kernel(const float* __restrict__ X,
                   const float* __restrict__ theta,
                   float* __restrict__ out) {
    __shared__ float buf[2][BUF];

    // blockIdx = b*256 + tile*4 + cg
    const int cg = blockIdx.x & (NCG - 1);
    const int t  = (blockIdx.x >> 2) & 63;
    const int b  = blockIdx.x >> 8;
    const int tx = (t & (NTX - 1)) * TILE;
    const int ty = (t >> 3) * TILE;

    const int lane = threadIdx.x & 31;
    const int w    = threadIdx.x >> 5;   // 0..7

    const float* th = theta + b * 6;
    const float t00 = __ldg(th + 0), t01 = __ldg(th + 1), t02 = __ldg(th + 2);
    const float t10 = __ldg(th + 3), t11 = __ldg(th + 4), t12 = __ldg(th + 5);

    // ---- tile bbox from the 4 tile corners (affine map is linear) + pad ----
    const float cxl = fmaf((float)tx,        2.0f / 255.0f, -1.0f);
    const float cxh = fmaf((float)(tx + 31), 2.0f / 255.0f, -1.0f);
    const float cyl = fmaf((float)ty,        2.0f / 255.0f, -1.0f);
    const float cyh = fmaf((float)(ty + 31), 2.0f / 255.0f, -1.0f);

    float xmn = 3.0e38f, xmx = -3.0e38f, ymn = 3.0e38f, ymx = -3.0e38f;
    #pragma unroll
    for (int k = 0; k < 4; ++k) {
        const float xck = (k & 1) ? cxh : cxl;
        const float yck = (k & 2) ? cyh : cyl;
        const float xs = t00 * xck + t01 * yck + t02;
        const float ys = t10 * xck + t11 * yck + t12;
        const float xx = (xs + 1.0f) * 128.0f;
        const float yy = (ys + 1.0f) * 128.0f;
        xmn = fminf(xmn, xx); xmx = fmaxf(xmx, xx);
        ymn = fminf(ymn, yy); ymx = fmaxf(ymx, yy);
    }
    const int xlo = min(max((int)floorf(xmn) - 1, 0), W - 1);
    const int xhi = min(max((int)floorf(xmx) + 2, 0), W - 1);
    const int ylo = min(max((int)floorf(ymn) - 1, 0), H - 1);
    const int yhi = min(max((int)floorf(ymx) + 2, 0), H - 1);
    const int bw  = xhi - xlo + 1;
    const int bh  = yhi - ylo + 1;
    const int bwp = bw | 1;              // odd stride vs LDS bank conflicts

    const float* __restrict__ xbase = X   + ((size_t)(b * C + cg * CG)) * HW;
    float*       __restrict__ obase = out + ((size_t)(b * C + cg * CG)) * HWO;

    const bool fits = (bwp * bh <= BUF);   // block-uniform

    if (fits) {
        // ===== staged path: mapping A (rows), double-buffered =====
        // thread -> pixels (tx+lane, ty + w + 8*i), i = 0..3
        int   la[4], lb[4], lc[4], ld[4];
        float wA[4], wB[4], wC[4], wD[4];
        #pragma unroll
        for (int i = 0; i < 4; ++i) {
            const int ix = tx + lane;
            const int iy = ty + w + 8 * i;

            const float xc = fmaf((float)ix, 2.0f / (float)(W_OUT - 1), -1.0f);
            const float yc = fmaf((float)iy, 2.0f / (float)(H_OUT - 1), -1.0f);
            const float xs = t00 * xc + t01 * yc + t02;
            const float ys = t10 * xc + t11 * yc + t12;
            const float x  = (xs + 1.0f) * ((float)W * 0.5f);
            const float y  = (ys + 1.0f) * ((float)H * 0.5f);

            int x0 = (int)floorf(x);
            int x1 = x0 + 1;
            int y0 = (int)floorf(y);
            int y1 = y0 + 1;
            x0 = min(max(x0, 0), W - 1);
            x1 = min(max(x1, 0), W - 1);
            y0 = min(max(y0, 0), H - 1);
            y1 = min(max(y1, 0), H - 1);

            const float x0f = (float)x0, x1f = (float)x1;
            const float y0f = (float)y0, y1f = (float)y1;
            wA[i] = (x1f - x) * (y1f - y);
            wB[i] = (x1f - x) * (y - y0f);
            wC[i] = (x - x0f) * (y1f - y);
            wD[i] = (x - x0f) * (y - y0f);
            la[i] = (y0 - ylo) * bwp + (x0 - xlo);
            lb[i] = (y1 - ylo) * bwp + (x0 - xlo);
            lc[i] = (y0 - ylo) * bwp + (x1 - xlo);
            ld[i] = (y1 - ylo) * bwp + (x1 - xlo);
        }

        // stage channel 0 into buf[0]
        {
            const float* src = xbase + (size_t)ylo * W + xlo;
            for (int r = w; r < bh; r += 8) {
                const float* sr = src + (size_t)r * W;
                float* dr = buf[0] + r * bwp;
                for (int q = lane; q < bw; q += 32)
                    dr[q] = __ldg(sr + q);
            }
        }

        for (int c = 0; c < CG; ++c) {
            __syncthreads();   // buf[c&1] fully staged; buf[(c+1)&1] free

            // stage next channel into the other buffer (overlaps gathers)
            if (c + 1 < CG) {
                const float* src = xbase + (size_t)(c + 1) * HW + (size_t)ylo * W + xlo;
                float* dst = buf[(c + 1) & 1];
                for (int r = w; r < bh; r += 8) {
                    const float* sr = src + (size_t)r * W;
                    float* dr = dst + r * bwp;
                    for (int q = lane; q < bw; q += 32)
                        dr[q] = __ldg(sr + q);
                }
            }

            // gather channel c from buf[c&1]
            const float* s = buf[c & 1];
            float* op = obase + (size_t)c * HWO + (size_t)(ty + w) * W_OUT + tx + lane;
            #pragma unroll
            for (int i = 0; i < 4; ++i) {
                const float pa = s[la[i]];
                const float pb = s[lb[i]];
                const float pc = s[lc[i]];
                const float pd = s[ld[i]];
                op[(size_t)(8 * i) * W_OUT] =
                    wA[i] * pa + wB[i] * pb + wC[i] * pc + wD[i] * pd;
            }
        }
    } else {
        // ===== fallback: direct gathers, R4-winning 8x4 warp patch =====
        const int lx = lane & 7;
        const int ly = lane >> 3;
        const int wx = w & 3;       // 4 warps across -> 32 wide
        const int wy = w >> 2;      // 2 warps down   -> 8 tall per i

        int   ga[4], gb[4], gc[4], gd[4];
        float wA[4], wB[4], wC[4], wD[4];
        #pragma unroll
        for (int i = 0; i < 4; ++i) {
            const int ix = tx + wx * 8 + lx;
            const int iy = ty + wy * 4 + ly + 8 * i;

            const float xc = fmaf((float)ix, 2.0f / (float)(W_OUT - 1), -1.0f);
            const float yc = fmaf((float)iy, 2.0f / (float)(H_OUT - 1), -1.0f);
            const float xs = t00 * xc + t01 * yc + t02;
            const float ys = t10 * xc + t11 * yc + t12;
            const float x  = (xs + 1.0f) * ((float)W * 0.5f);
            const float y  = (ys + 1.0f) * ((float)H * 0.5f);

            int x0 = (int)floorf(x);
            int x1 = x0 + 1;
            int y0 = (int)floorf(y);
            int y1 = y0 + 1;
            x0 = min(max(x0, 0), W - 1);
            x1 = min(max(x1, 0), W - 1);
            y0 = min(max(y0, 0), H - 1);
            y1 = min(max(y1, 0), H - 1);

            const float x0f = (float)x0, x1f = (float)x1;
            const float y0f = (float)y0, y1f = (float)y1;
            wA[i] = (x1f - x) * (y1f - y);
            wB[i] = (x1f - x) * (y - y0f);
            wC[i] = (x - x0f) * (y1f - y);
            wD[i] = (x - x0f) * (y - y0f);
            ga[i] = y0 * W + x0;
            gb[i] = y1 * W + x0;
            gc[i] = y0 * W + x1;
            gd[i] = y1 * W + x1;
        }

        const int ox = tx + wx * 8 + lx;
        const int oy = ty + wy * 4 + ly;
        for (int c = 0; c < CG; ++c) {
            const float* p = xbase + (size_t)c * HW;
            float* op = obase + (size_t)c * HWO + (size_t)oy * W_OUT + ox;
            #pragma unroll
            for (int i = 0; i < 4; ++i) {
                const float pa = __ldg(p + ga[i]);
                const float pb = __ldg(p + gb[i]);
                const float pc = __ldg(p + gc[i]);
                const float pd = __ldg(p + gd[i]);
                op[(size_t)(8 * i) * W_OUT] =
                    wA[i] * pa + wB[i] * pb + wC[i] * pc + wD[i] * pd;
            }
        }
    }
}

extern "C" void kernel_launch(void* const* d_in, const int* in_sizes, int n_in,
                              void* d_out, int out_size) {
    const float* X     = (const float*)d_in[0];
    const float* theta = (const float*)d_in[1];
    if (n_in >= 2 && in_sizes[0] == B * 6) {
        theta = (const float*)d_in[0];
        X     = (const float*)d_in[1];
    }
    float* out = (float*)d_out;

    dim3 grid(B * 64 * NCG);   // 4096 blocks
    dim3 block(256);
    bilerp_kernel<<<grid, block>>>(X, theta, out);
}

// round 10
// speedup vs baseline: 1.8826x; 1.7901x over previous
#include <cuda_runtime.h>
#include <cuda_bf16.h>
#include <cstdint>

// BilinearInterpolation (spatial transformer grid sample)
// X: [B, C, H, W] fp32, theta: [B, 6] fp32 -> out: [B, C, H_OUT, W_OUT] fp32
//
// R9 = R8 (double-buffered smem staging) with the staging path rebuilt on
// cp.async.cg 16B (LDGSTS): no dest register, no scoreboard dependency, so
// the dynamic-trip-count staging loop no longer serializes at MLP~1.
// bbox is 16B-aligned (xlo & ~3, 4-float chunks, smem row stride %4==0).
// One commit group + one barrier per channel keeps the ping-pong correct.
// Staged values are bit-exact copies; weight chain identical to R2-R4:
// rel_err must stay exactly 9.128e-4.

namespace {
constexpr int B = 16, C = 64, H = 256, W = 256;
constexpr int H_OUT = 256, W_OUT = 256;
constexpr int HW  = H * W;
constexpr int HWO = H_OUT * W_OUT;
constexpr int TILE = 32;            // 32x32 output tile
constexpr int CG   = 16;            // channels per block
constexpr int NCG  = C / CG;        // 4
constexpr int NTX  = W_OUT / TILE;  // 8
constexpr int BUF  = 6080;          // floats per buffer; 2 bufs = 47.5KB
}

__device__ __forceinline__ void cp_async16(uint32_t smem_addr, const void* gptr) {
    asm volatile("cp.async.cg.shared.global [%0], [%1], 16;\n"
                 :: "r"(smem_addr), "l"(gptr));
}
__device__ __forceinline__ void cp_async_commit() {
    asm volatile("cp.async.commit_group;\n" ::: "memory");
}
__device__ __forceinline__ void cp_async_wait_all() {
    asm volatile("cp.async.wait_group 0;\n" ::: "memory");
}

__global__ __launch_bounds__(256, 4)
void bilerp_kernel(const float* __restrict__ X,
                   const float* __restrict__ theta,
                   float* __restrict__ out) {
    __shared__ __align__(16) float buf[2][BUF];

    // blockIdx = b*256 + tile*4 + cg
    const int cg = blockIdx.x & (NCG - 1);
    const int t  = (blockIdx.x >> 2) & 63;
    const int b  = blockIdx.x >> 8;
    const int tx = (t & (NTX - 1)) * TILE;
    const int ty = (t >> 3) * TILE;

    const int lane = threadIdx.x & 31;
    const int w    = threadIdx.x >> 5;   // 0..7

    const float* th = theta + b * 6;
    const float t00 = __ldg(th + 0), t01 = __ldg(th + 1), t02 = __ldg(th + 2);
    const float t10 = __ldg(th + 3), t11 = __ldg(th + 4), t12 = __ldg(th + 5);

    // ---- tile bbox from the 4 tile corners (affine map is linear) + pad ----
    const float cxl = fmaf((float)tx,        2.0f / 255.0f, -1.0f);
    const float cxh = fmaf((float)(tx + 31), 2.0f / 255.0f, -1.0f);
    const float cyl = fmaf((float)ty,        2.0f / 255.0f, -1.0f);
    const float cyh = fmaf((float)(ty + 31), 2.0f / 255.0f, -1.0f);

    float xmn = 3.0e38f, xmx = -3.0e38f, ymn = 3.0e38f, ymx = -3.0e38f;
    #pragma unroll
    for (int k = 0; k < 4; ++k) {
        const float xck = (k & 1) ? cxh : cxl;
        const float yck = (k & 2) ? cyh : cyl;
        const float xs = t00 * xck + t01 * yck + t02;
        const float ys = t10 * xck + t11 * yck + t12;
        const float xx = (xs + 1.0f) * 128.0f;
        const float yy = (ys + 1.0f) * 128.0f;
        xmn = fminf(xmn, xx); xmx = fmaxf(xmx, xx);
        ymn = fminf(ymn, yy); ymx = fmaxf(ymx, yy);
    }
    const int xlo = min(max((int)floorf(xmn) - 1, 0), W - 1);
    const int xhi = min(max((int)floorf(xmx) + 2, 0), W - 1);
    const int ylo = min(max((int)floorf(ymn) - 1, 0), H - 1);
    const int yhi = min(max((int)floorf(ymx) + 2, 0), H - 1);

    // 16B-aligned staging window (W row base is 1KB-aligned)
    const int xlo4 = xlo & ~3;
    const int bw4  = ((xhi - xlo4) | 3) + 1;   // multiple of 4, covers xhi
    const int bh   = yhi - ylo + 1;
    const int bwp  = bw4 + 4;                  // stride %4==0, offset vs bank wrap
    const int nch  = bw4 >> 2;                 // 16B chunks per row

    const float* __restrict__ xbase = X   + ((size_t)(b * C + cg * CG)) * HW;
    float*       __restrict__ obase = out + ((size_t)(b * C + cg * CG)) * HWO;

    const bool fits = (bwp * bh <= BUF);   // block-uniform

    if (fits) {
        // ===== staged path, cp.async double-buffered =====
        // thread -> pixels (tx+lane, ty + w + 8*i), i = 0..3
        int   la[4], lb[4], lc[4], ld[4];
        float wA[4], wB[4], wC[4], wD[4];
        #pragma unroll
        for (int i = 0; i < 4; ++i) {
            const int ix = tx + lane;
            const int iy = ty + w + 8 * i;

            const float xc = fmaf((float)ix, 2.0f / (float)(W_OUT - 1), -1.0f);
            const float yc = fmaf((float)iy, 2.0f / (float)(H_OUT - 1), -1.0f);
            const float xs = t00 * xc + t01 * yc + t02;
            const float ys = t10 * xc + t11 * yc + t12;
            const float x  = (xs + 1.0f) * ((float)W * 0.5f);
            const float y  = (ys + 1.0f) * ((float)H * 0.5f);

            int x0 = (int)floorf(x);
            int x1 = x0 + 1;
            int y0 = (int)floorf(y);
            int y1 = y0 + 1;
            x0 = min(max(x0, 0), W - 1);
            x1 = min(max(x1, 0), W - 1);
            y0 = min(max(y0, 0), H - 1);
            y1 = min(max(y1, 0), H - 1);

            const float x0f = (float)x0, x1f = (float)x1;
            const float y0f = (float)y0, y1f = (float)y1;
            wA[i] = (x1f - x) * (y1f - y);
            wB[i] = (x1f - x) * (y - y0f);
            wC[i] = (x - x0f) * (y1f - y);
            wD[i] = (x - x0f) * (y - y0f);
            la[i] = (y0 - ylo) * bwp + (x0 - xlo4);
            lb[i] = (y1 - ylo) * bwp + (x0 - xlo4);
            lc[i] = (y0 - ylo) * bwp + (x1 - xlo4);
            ld[i] = (y1 - ylo) * bwp + (x1 - xlo4);
        }

        uint32_t sbase[2];
        sbase[0] = (uint32_t)__cvta_generic_to_shared(&buf[0][0]);
        sbase[1] = (uint32_t)__cvta_generic_to_shared(&buf[1][0]);

        // stage channel 0 into buf[0]
        {
            const float* src = xbase + (size_t)ylo * W + xlo4;
            for (int r = w; r < bh; r += 8) {
                const float* sr = src + (size_t)r * W;
                const uint32_t dr = sbase[0] + (uint32_t)(r * bwp) * 4u;
                for (int q = lane; q < nch; q += 32)
                    cp_async16(dr + (uint32_t)q * 16u, sr + q * 4);
            }
            cp_async_commit();
        }

        for (int c = 0; c < CG; ++c) {
            cp_async_wait_all();   // this thread's copies into buf[c&1] done
            __syncthreads();       // all threads' copies done; prev gathers done

            // stage next channel into the other buffer (async, overlapped)
            if (c + 1 < CG) {
                const float* src = xbase + (size_t)(c + 1) * HW + (size_t)ylo * W + xlo4;
                const uint32_t db = sbase[(c + 1) & 1];
                for (int r = w; r < bh; r += 8) {
                    const float* sr = src + (size_t)r * W;
                    const uint32_t dr = db + (uint32_t)(r * bwp) * 4u;
                    for (int q = lane; q < nch; q += 32)
                        cp_async16(dr + (uint32_t)q * 16u, sr + q * 4);
                }
                cp_async_commit();
            }

            // gather channel c from buf[c&1]
            const float* s = buf[c & 1];
            float* op = obase + (size_t)c * HWO + (size_t)(ty + w) * W_OUT + tx + lane;
            #pragma unroll
            for (int i = 0; i < 4; ++i) {
                const float pa = s[la[i]];
                const float pb = s[lb[i]];
                const float pc = s[lc[i]];
                const float pd = s[ld[i]];
                op[(size_t)(8 * i) * W_OUT] =
                    wA[i] * pa + wB[i] * pb + wC[i] * pc + wD[i] * pd;
            }
        }
    } else {
        // ===== fallback: direct gathers, R4-winning 8x4 warp patch =====
        const int lx = lane & 7;
        const int ly = lane >> 3;
        const int wx = w & 3;
        const int wy = w >> 2;

        int   ga[4], gb[4], gc[4], gd[4];
        float wA[4], wB[4], wC[4], wD[4];
        #pragma unroll
        for (int i = 0; i < 4; ++i) {
            const int ix = tx + wx * 8 + lx;
            const int iy = ty + wy * 4 + ly + 8 * i;

            const float xc = fmaf((float)ix, 2.0f / (float)(W_OUT - 1), -1.0f);
            const float yc = fmaf((float)iy, 2.0f / (float)(H_OUT - 1), -1.0f);
            const float xs = t00 * xc + t01 * yc + t02;
            const float ys = t10 * xc + t11 * yc + t12;
            const float x  = (xs + 1.0f) * ((float)W * 0.5f);
            const float y  = (ys + 1.0f) * ((float)H * 0.5f);

            int x0 = (int)floorf(x);
            int x1 = x0 + 1;
            int y0 = (int)floorf(y);
            int y1 = y0 + 1;
            x0 = min(max(x0, 0), W - 1);
            x1 = min(max(x1, 0), W - 1);
            y0 = min(max(y0, 0), H - 1);
            y1 = min(max(y1, 0), H - 1);

            const float x0f = (float)x0, x1f = (float)x1;
            const float y0f = (float)y0, y1f = (float)y1;
            wA[i] = (x1f - x) * (y1f - y);
            wB[i] = (x1f - x) * (y - y0f);
            wC[i] = (x - x0f) * (y1f - y);
            wD[i] = (x - x0f) * (y - y0f);
            ga[i] = y0 * W + x0;
            gb[i] = y1 * W + x0;
            gc[i] = y0 * W + x1;
            gd[i] = y1 * W + x1;
        }

        const int ox = tx + wx * 8 + lx;
        const int oy = ty + wy * 4 + ly;
        for (int c = 0; c < CG; ++c) {
            const float* p = xbase + (size_t)c * HW;
            float* op = obase + (size_t)c * HWO + (size_t)oy * W_OUT + ox;
            #pragma unroll
            for (int i = 0; i < 4; ++i) {
                const float pa = __ldg(p + ga[i]);
                const float pb = __ldg(p + gb[i]);
                const float pc = __ldg(p + gc[i]);
                const float pd = __ldg(p + gd[i]);
                op[(size_t)(8 * i) * W_OUT] =
                    wA[i] * pa + wB[i] * pb + wC[i] * pc + wD[i] * pd;
            }
        }
    }
}

extern "C" void kernel_launch(void* const* d_in, const int* in_sizes, int n_in,
                              void* d_out, int out_size) {
    const float* X     = (const float*)d_in[0];
    const float* theta = (const float*)d_in[1];
    if (n_in >= 2 && in_sizes[0] == B * 6) {
        theta = (const float*)d_in[0];
        X     = (const float*)d_in[1];
    }
    float* out = (float*)d_out;

    dim3 grid(B * 64 * NCG);   // 4096 blocks
    dim3 block(256);
    bilerp_kernel<<<grid, block>>>(X, theta, out);
}

// round 11
// speedup vs baseline: 1.9616x; 1.0419x over previous
#include <cuda_runtime.h>
#include <cuda_bf16.h>
#include <cstdint>

// BilinearInterpolation (spatial transformer grid sample)
// X: [B, C, H, W] fp32, theta: [B, 6] fp32 -> out: [B, C, H_OUT, W_OUT] fp32
//
// R10 = R9 (cp.async double-buffered smem staging) with issue-count surgery:
//  - flat predicated staging loop (pow2-rounded chunks, one idx loop over
//    256 threads) instead of nested dynamic loops  (~3x fewer staging instr)
//  - channel loop advanced by 2 with static buffer parity (smem LDS bases
//    become compile-time, address adds fold into LDS immediates)
//  - BUF 6080->5632 floats + launch_bounds(256,5): 5 blocks/SM, ~60% occ
// Staged values are bit-exact copies; weight chain identical to R2-R4:
// rel_err must stay exactly 9.128e-4.

namespace {
constexpr int B = 16, C = 64, H = 256, W = 256;
constexpr int H_OUT = 256, W_OUT = 256;
constexpr int HW  = H * W;
constexpr int HWO = H_OUT * W_OUT;
constexpr int TILE = 32;            // 32x32 output tile
constexpr int CG   = 16;            // channels per block
constexpr int NCG  = C / CG;        // 4
constexpr int NTX  = W_OUT / TILE;  // 8
constexpr int BUF  = 5632;          // floats per buffer; 2 bufs = 45KB
}

__device__ __forceinline__ void cp_async16(uint32_t smem_addr, const void* gptr) {
    asm volatile("cp.async.cg.shared.global [%0], [%1], 16;\n"
                 :: "r"(smem_addr), "l"(gptr));
}
__device__ __forceinline__ void cp_async_commit() {
    asm volatile("cp.async.commit_group;\n" ::: "memory");
}
__device__ __forceinline__ void cp_async_wait_all() {
    asm volatile("cp.async.wait_group 0;\n" ::: "memory");
}

__global__ __launch_bounds__(256, 5)
void bilerp_kernel(const float* __restrict__ X,
                   const float* __restrict__ theta,
                   float* __restrict__ out) {
    __shared__ __align__(16) float buf0[BUF];
    __shared__ __align__(16) float buf1[BUF];

    // blockIdx = b*256 + tile*4 + cg
    const int cg = blockIdx.x & (NCG - 1);
    const int t  = (blockIdx.x >> 2) & 63;
    const int b  = blockIdx.x >> 8;
    const int tx = (t & (NTX - 1)) * TILE;
    const int ty = (t >> 3) * TILE;

    const int lane = threadIdx.x & 31;
    const int w    = threadIdx.x >> 5;   // 0..7

    const float* th = theta + b * 6;
    const float t00 = __ldg(th + 0), t01 = __ldg(th + 1), t02 = __ldg(th + 2);
    const float t10 = __ldg(th + 3), t11 = __ldg(th + 4), t12 = __ldg(th + 5);

    // ---- tile bbox from the 4 tile corners (affine map is linear) + pad ----
    const float cxl = fmaf((float)tx,        2.0f / 255.0f, -1.0f);
    const float cxh = fmaf((float)(tx + 31), 2.0f / 255.0f, -1.0f);
    const float cyl = fmaf((float)ty,        2.0f / 255.0f, -1.0f);
    const float cyh = fmaf((float)(ty + 31), 2.0f / 255.0f, -1.0f);

    float xmn = 3.0e38f, xmx = -3.0e38f, ymn = 3.0e38f, ymx = -3.0e38f;
    #pragma unroll
    for (int k = 0; k < 4; ++k) {
        const float xck = (k & 1) ? cxh : cxl;
        const float yck = (k & 2) ? cyh : cyl;
        const float xs = t00 * xck + t01 * yck + t02;
        const float ys = t10 * xck + t11 * yck + t12;
        const float xx = (xs + 1.0f) * 128.0f;
        const float yy = (ys + 1.0f) * 128.0f;
        xmn = fminf(xmn, xx); xmx = fmaxf(xmx, xx);
        ymn = fminf(ymn, yy); ymx = fmaxf(ymx, yy);
    }
    const int xlo = min(max((int)floorf(xmn) - 1, 0), W - 1);
    const int xhi = min(max((int)floorf(xmx) + 2, 0), W - 1);
    const int ylo = min(max((int)floorf(ymn) - 1, 0), H - 1);
    const int yhi = min(max((int)floorf(ymx) + 2, 0), H - 1);

    // 16B-aligned staging window (X rows are 1KB-aligned)
    const int xlo4 = xlo & ~3;
    const int bw4  = ((xhi - xlo4) | 3) + 1;   // multiple of 4, covers xhi
    const int bh   = yhi - ylo + 1;
    const int bwp  = bw4 + 4;                  // stride %4==0, skews banks
    const int nch  = bw4 >> 2;                 // 16B chunks per row (>=1)

    const float* __restrict__ xbase = X   + ((size_t)(b * C + cg * CG)) * HW;
    float*       __restrict__ obase = out + ((size_t)(b * C + cg * CG)) * HWO;

    const bool fits = (bwp * bh <= BUF);   // block-uniform

    if (fits) {
        // ===== staged path =====
        // thread -> pixels (tx+lane, ty + w + 8*i), i = 0..3
        int   la[4], lb[4], lc[4], ld[4];
        float wA[4], wB[4], wC[4], wD[4];
        #pragma unroll
        for (int i = 0; i < 4; ++i) {
            const int ix = tx + lane;
            const int iy = ty + w + 8 * i;

            const float xc = fmaf((float)ix, 2.0f / (float)(W_OUT - 1), -1.0f);
            const float yc = fmaf((float)iy, 2.0f / (float)(H_OUT - 1), -1.0f);
            const float xs = t00 * xc + t01 * yc + t02;
            const float ys = t10 * xc + t11 * yc + t12;
            const float x  = (xs + 1.0f) * ((float)W * 0.5f);
            const float y  = (ys + 1.0f) * ((float)H * 0.5f);

            int x0 = (int)floorf(x);
            int x1 = x0 + 1;
            int y0 = (int)floorf(y);
            int y1 = y0 + 1;
            x0 = min(max(x0, 0), W - 1);
            x1 = min(max(x1, 0), W - 1);
            y0 = min(max(y0, 0), H - 1);
            y1 = min(max(y1, 0), H - 1);

            const float x0f = (float)x0, x1f = (float)x1;
            const float y0f = (float)y0, y1f = (float)y1;
            wA[i] = (x1f - x) * (y1f - y);
            wB[i] = (x1f - x) * (y - y0f);
            wC[i] = (x - x0f) * (y1f - y);
            wD[i] = (x - x0f) * (y - y0f);
            la[i] = (y0 - ylo) * bwp + (x0 - xlo4);
            lb[i] = (y1 - ylo) * bwp + (x0 - xlo4);
            lc[i] = (y0 - ylo) * bwp + (x1 - xlo4);
            ld[i] = (y1 - ylo) * bwp + (x1 - xlo4);
        }

        // flat staging: pow2-rounded chunk grid, predicated cp.async
        const int ls   = (nch > 1) ? (32 - __clz(nch - 1)) : 0;  // ceil log2
        const int nch2m = (1 << ls) - 1;
        const int tot  = bh << ls;
        const uint32_t sb0 = (uint32_t)__cvta_generic_to_shared(buf0);
        const uint32_t sb1 = (uint32_t)__cvta_generic_to_shared(buf1);
        const int tid = threadIdx.x;

        auto stage = [&](int c, uint32_t db) {
            const float* src = xbase + (size_t)c * HW + (size_t)ylo * W + xlo4;
            for (int idx = tid; idx < tot; idx += 256) {
                const int r = idx >> ls;
                const int q = idx & nch2m;
                if (q < nch)
                    cp_async16(db + (uint32_t)(r * bwp) * 4u + (uint32_t)q * 16u,
                               src + (size_t)r * W + q * 4);
            }
            cp_async_commit();
        };

        const size_t orow = (size_t)(ty + w) * W_OUT + tx + lane;

        stage(0, sb0);
        #pragma unroll
        for (int cc = 0; cc < CG; cc += 2) {
            // ---- even channel: gather from buf0 ----
            cp_async_wait_all();
            __syncthreads();
            if (cc + 1 < CG) stage(cc + 1, sb1);
            {
                float* op = obase + (size_t)cc * HWO + orow;
                #pragma unroll
                for (int i = 0; i < 4; ++i) {
                    const float pa = buf0[la[i]];
                    const float pb = buf0[lb[i]];
                    const float pc = buf0[lc[i]];
                    const float pd = buf0[ld[i]];
                    op[(size_t)(8 * i) * W_OUT] =
                        wA[i] * pa + wB[i] * pb + wC[i] * pc + wD[i] * pd;
                }
            }
            // ---- odd channel: gather from buf1 ----
            cp_async_wait_all();
            __syncthreads();
            if (cc + 2 < CG) stage(cc + 2, sb0);
            {
                float* op = obase + (size_t)(cc + 1) * HWO + orow;
                #pragma unroll
                for (int i = 0; i < 4; ++i) {
                    const float pa = buf1[la[i]];
                    const float pb = buf1[lb[i]];
                    const float pc = buf1[lc[i]];
                    const float pd = buf1[ld[i]];
                    op[(size_t)(8 * i) * W_OUT] =
                        wA[i] * pa + wB[i] * pb + wC[i] * pc + wD[i] * pd;
                }
            }
        }
    } else {
        // ===== fallback: direct gathers, R4-winning 8x4 warp patch =====
        const int lx = lane & 7;
        const int ly = lane >> 3;
        const int wx = w & 3;
        const int wy = w >> 2;

        int   ga[4], gb[4], gc[4], gd[4];
        float wA[4], wB[4], wC[4], wD[4];
        #pragma unroll
        for (int i = 0; i < 4; ++i) {
            const int ix = tx + wx * 8 + lx;
            const int iy = ty + wy * 4 + ly + 8 * i;

            const float xc = fmaf((float)ix, 2.0f / (float)(W_OUT - 1), -1.0f);
            const float yc = fmaf((float)iy, 2.0f / (float)(H_OUT - 1), -1.0f);
            const float xs = t00 * xc + t01 * yc + t02;
            const float ys = t10 * xc + t11 * yc + t12;
            const float x  = (xs + 1.0f) * ((float)W * 0.5f);
            const float y  = (ys + 1.0f) * ((float)H * 0.5f);

            int x0 = (int)floorf(x);
            int x1 = x0 + 1;
            int y0 = (int)floorf(y);
            int y1 = y0 + 1;
            x0 = min(max(x0, 0), W - 1);
            x1 = min(max(x1, 0), W - 1);
            y0 = min(max(y0, 0), H - 1);
            y1 = min(max(y1, 0), H - 1);

            const float x0f = (float)x0, x1f = (float)x1;
            const float y0f = (float)y0, y1f = (float)y1;
            wA[i] = (x1f - x) * (y1f - y);
            wB[i] = (x1f - x) * (y - y0f);
            wC[i] = (x - x0f) * (y1f - y);
            wD[i] = (x - x0f) * (y - y0f);
            ga[i] = y0 * W + x0;
            gb[i] = y1 * W + x0;
            gc[i] = y0 * W + x1;
            gd[i] = y1 * W + x1;
        }

        const int ox = tx + wx * 8 + lx;
        const int oy = ty + wy * 4 + ly;
        for (int c = 0; c < CG; ++c) {
            const float* p = xbase + (size_t)c * HW;
            float* op = obase + (size_t)c * HWO + (size_t)oy * W_OUT + ox;
            #pragma unroll
            for (int i = 0; i < 4; ++i) {
                const float pa = __ldg(p + ga[i]);
                const float pb = __ldg(p + gb[i]);
                const float pc = __ldg(p + gc[i]);
                const float pd = __ldg(p + gd[i]);
                op[(size_t)(8 * i) * W_OUT] =
                    wA[i] * pa + wB[i] * pb + wC[i] * pc + wD[i] * pd;
            }
        }
    }
}

extern "C" void kernel_launch(void* const* d_in, const int* in_sizes, int n_in,
                              void* d_out, int out_size) {
    const float* X     = (const float*)d_in[0];
    const float* theta = (const float*)d_in[1];
    if (n_in >= 2 && in_sizes[0] == B * 6) {
        theta = (const float*)d_in[0];
        X     = (const float*)d_in[1];
    }
    float* out = (float*)d_out;

    dim3 grid(B * 64 * NCG);   // 4096 blocks
    dim3 block(256);
    bilerp_kernel<<<grid, block>>>(X, theta, out);
}